// round 1
// baseline (speedup 1.0000x reference)
#include <cuda_runtime.h>
#include <cuda_bf16.h>
#include <math.h>

// ============================================================================
// DMAModel: 2-layer weighted GAT + link scoring.
//   Layer(h, W, as, ad): h1 = h@W; e_ij = lrelu(h1 as)_i + (h1 ad)_j (adj-masked)
//   att = softmax(e); out = elu((att*w) @ h1), w = 0.5*amount + 0.5*count
//   logits_p = (h2 @ Wb)[i_p] . h2[j_p] + bb ; out = sigmoid(logits)
//
// Key insight: adj is ~1% dense; att*w == 0 off-adjacency and masked entries
// contribute exactly 0.0f to the softmax denominator (expf underflow). So we
// build a compact neighbor list once and do sparse attention + SpMM.
// ============================================================================

#define N_NODES 4096
#define D_IN    256
#define D_HID   512
#define D_OUT   256
#define CAP     512        // max neighbors per row (mean ~41; 512 is far past any tail)

// ---------------- scratch (device globals; no allocation allowed) -----------
__device__ float g_h1 [N_NODES * D_HID];   // x @ W1
__device__ float g_o1 [N_NODES * D_HID];   // layer-1 output
__device__ float g_h2 [N_NODES * D_OUT];   // o1 @ W2
__device__ float g_o2 [N_NODES * D_OUT];   // layer-2 output (== final h)
__device__ float g_hb [N_NODES * D_OUT];   // o2 @ Wb
__device__ float g_src[N_NODES];
__device__ float g_dst[N_NODES];
__device__ int   g_cols[(size_t)N_NODES * CAP];
__device__ float g_wv  [(size_t)N_NODES * CAP];
__device__ int   g_cnt [N_NODES];

// ---------------- sparse structure build (deterministic, ordered) -----------
// One block per row. Ordered stream compaction via ballot + warp prefix so the
// neighbor list is always in ascending-j order (bitwise deterministic).
__global__ void build_sparse_k(const float* __restrict__ adj,
                               const float* __restrict__ amount,
                               const float* __restrict__ count)
{
    const int i   = blockIdx.x;
    const int tid = threadIdx.x;           // 256 threads
    const int lane = tid & 31, warp = tid >> 5;
    const float* arow = adj + (size_t)i * N_NODES;

    __shared__ int s_cnt;
    __shared__ int s_wc[8];
    __shared__ int s_woff[8];
    if (tid == 0) s_cnt = 0;
    __syncthreads();

    for (int base = 0; base < N_NODES; base += 256) {
        const int j = base + tid;
        const bool p = arow[j] > 0.0f;
        const unsigned bal = __ballot_sync(0xffffffffu, p);
        const int wprefix = __popc(bal & ((1u << lane) - 1u));
        if (lane == 0) s_wc[warp] = __popc(bal);
        __syncthreads();
        if (tid == 0) {
            int off = s_cnt;
            #pragma unroll
            for (int w = 0; w < 8; w++) { s_woff[w] = off; off += s_wc[w]; }
            s_cnt = off;
        }
        __syncthreads();
        if (p) {
            const int k = s_woff[warp] + wprefix;
            if (k < CAP) {
                g_cols[(size_t)i * CAP + k] = j;
                g_wv  [(size_t)i * CAP + k] =
                    0.5f * (amount[(size_t)i * N_NODES + j] +
                            count [(size_t)i * N_NODES + j]);
            }
        }
        __syncthreads();
    }
    if (tid == 0) g_cnt[i] = min(s_cnt, CAP);
}

// ---------------- per-row (h@a_src, h@a_dst) ---------------------------------
__global__ void rowdots_k(const float* __restrict__ h,
                          const float* __restrict__ asrc,
                          const float* __restrict__ adst,
                          int D)
{
    const int i = blockIdx.x;
    const int tid = threadIdx.x;           // 128 threads
    float s1 = 0.0f, s2 = 0.0f;
    const float* hr = h + (size_t)i * D;
    for (int d = tid; d < D; d += 128) {
        const float v = hr[d];
        s1 += v * asrc[d];
        s2 += v * adst[d];
    }
    __shared__ float r1[128], r2[128];
    r1[tid] = s1; r2[tid] = s2;
    __syncthreads();
    for (int s = 64; s > 0; s >>= 1) {
        if (tid < s) { r1[tid] += r1[tid + s]; r2[tid] += r2[tid + s]; }
        __syncthreads();
    }
    if (tid == 0) { g_src[i] = r1[0]; g_dst[i] = r2[0]; }
}

// ---------------- fused sparse attention softmax + SpMM + ELU ----------------
// One block (256 threads) per row i:
//   e_k = lrelu(src_i + dst[col_k]); p_k = exp(e_k-max)/sum * w_k
//   out[i,:] = elu( sum_k p_k * h[col_k,:] )
__global__ void attn_spmm_k(const float* __restrict__ h,
                            float* __restrict__ out, int D)
{
    const int i = blockIdx.x;
    const int tid = threadIdx.x;           // 256 threads
    const int cnt = g_cnt[i];

    __shared__ int   s_col[CAP];
    __shared__ float s_p  [CAP];
    __shared__ float red  [256];

    const float si = g_src[i];
    float lmax = -3.4e38f;
    for (int k = tid; k < cnt; k += 256) {
        const int c = g_cols[(size_t)i * CAP + k];
        s_col[k] = c;
        float e = si + g_dst[c];
        e = (e >= 0.0f) ? e : 0.2f * e;
        s_p[k] = e;
        lmax = fmaxf(lmax, e);
    }
    red[tid] = lmax;
    __syncthreads();
    for (int s = 128; s > 0; s >>= 1) {
        if (tid < s) red[tid] = fmaxf(red[tid], red[tid + s]);
        __syncthreads();
    }
    const float m = red[0];
    __syncthreads();

    float lsum = 0.0f;
    for (int k = tid; k < cnt; k += 256) {
        const float ex = expf(s_p[k] - m);
        s_p[k] = ex;
        lsum += ex;
    }
    red[tid] = lsum;
    __syncthreads();
    for (int s = 128; s > 0; s >>= 1) {
        if (tid < s) red[tid] += red[tid + s];
        __syncthreads();
    }
    const float inv = (cnt > 0) ? (1.0f / red[0]) : 0.0f;
    __syncthreads();

    for (int k = tid; k < cnt; k += 256)
        s_p[k] = s_p[k] * inv * g_wv[(size_t)i * CAP + k];
    __syncthreads();

    for (int d = tid; d < D; d += 256) {
        float acc = 0.0f;
        for (int k = 0; k < cnt; k++)
            acc += s_p[k] * h[(size_t)s_col[k] * D + d];
        out[(size_t)i * D + d] = (acc > 0.0f) ? acc : expm1f(acc);
    }
}

// ---------------- SGEMM: C[M,N] = A[M,K] @ B[K,N] ----------------------------
// 128x64 block tile, 8x4 per-thread microtile, BK=16, 256 threads.
// All problem dims here are multiples of the tile dims (no bounds checks).
#define BM 128
#define BN 64
#define BK 16
#define TM 8
#define TN 4
__global__ __launch_bounds__(256) void sgemm_k(const float* __restrict__ A,
                                               const float* __restrict__ B,
                                               float* __restrict__ C,
                                               int M, int N, int K)
{
    __shared__ float As[BK][BM];
    __shared__ float Bs[BK][BN];
    const int bm = blockIdx.y * BM;
    const int bn = blockIdx.x * BN;
    const int tid = threadIdx.x;
    const int tx = tid & 15;       // n-dir, 16 threads
    const int ty = tid >> 4;       // m-dir, 16 threads

    const int aRow = tid >> 2;           // 0..63
    const int aCol = (tid & 3) * 4;      // 0,4,8,12
    const int bRow = tid >> 4;           // 0..15
    const int bCol = (tid & 15) * 4;     // 0..60

    float acc[TM][TN];
    #pragma unroll
    for (int ii = 0; ii < TM; ii++)
        #pragma unroll
        for (int jj = 0; jj < TN; jj++) acc[ii][jj] = 0.0f;

    for (int k0 = 0; k0 < K; k0 += BK) {
        const float4 a0 = *(const float4*)(A + (size_t)(bm + aRow)      * K + k0 + aCol);
        const float4 a1 = *(const float4*)(A + (size_t)(bm + aRow + 64) * K + k0 + aCol);
        As[aCol + 0][aRow]      = a0.x; As[aCol + 1][aRow]      = a0.y;
        As[aCol + 2][aRow]      = a0.z; As[aCol + 3][aRow]      = a0.w;
        As[aCol + 0][aRow + 64] = a1.x; As[aCol + 1][aRow + 64] = a1.y;
        As[aCol + 2][aRow + 64] = a1.z; As[aCol + 3][aRow + 64] = a1.w;
        *(float4*)&Bs[bRow][bCol] =
            *(const float4*)(B + (size_t)(k0 + bRow) * N + bn + bCol);
        __syncthreads();

        #pragma unroll
        for (int k = 0; k < BK; k++) {
            const float4 av0 = *(const float4*)&As[k][ty * TM];
            const float4 av1 = *(const float4*)&As[k][ty * TM + 4];
            const float4 bv  = *(const float4*)&Bs[k][tx * TN];
            const float a[TM] = {av0.x, av0.y, av0.z, av0.w, av1.x, av1.y, av1.z, av1.w};
            const float b[TN] = {bv.x, bv.y, bv.z, bv.w};
            #pragma unroll
            for (int ii = 0; ii < TM; ii++)
                #pragma unroll
                for (int jj = 0; jj < TN; jj++)
                    acc[ii][jj] += a[ii] * b[jj];
        }
        __syncthreads();
    }

    #pragma unroll
    for (int ii = 0; ii < TM; ii++) {
        float4 v = make_float4(acc[ii][0], acc[ii][1], acc[ii][2], acc[ii][3]);
        *(float4*)(C + (size_t)(bm + ty * TM + ii) * N + bn + tx * TN) = v;
    }
}

// ---------------- pair scoring: sigmoid(H[i].h[j] + bb) ----------------------
__global__ void pairs_k(const int* __restrict__ pairs,
                        const float* __restrict__ bb,
                        float* __restrict__ out, int P)
{
    const int wid  = (blockIdx.x * blockDim.x + threadIdx.x) >> 5;
    const int lane = threadIdx.x & 31;
    if (wid >= P) return;
    const int i = pairs[2 * wid + 0];
    const int j = pairs[2 * wid + 1];
    const float4* ra = (const float4*)(g_hb + (size_t)i * D_OUT);
    const float4* rb = (const float4*)(g_o2 + (size_t)j * D_OUT);
    float s = 0.0f;
    #pragma unroll
    for (int t = lane; t < D_OUT / 4; t += 32) {
        const float4 a = ra[t], b = rb[t];
        s += a.x * b.x + a.y * b.y + a.z * b.z + a.w * b.w;
    }
    #pragma unroll
    for (int o = 16; o > 0; o >>= 1) s += __shfl_down_sync(0xffffffffu, s, o);
    if (lane == 0) out[wid] = 1.0f / (1.0f + expf(-(s + bb[0])));
}

// ============================================================================
extern "C" void kernel_launch(void* const* d_in, const int* in_sizes, int n_in,
                              void* d_out, int out_size)
{
    const float* x      = (const float*)d_in[0];
    const float* adj    = (const float*)d_in[1];
    const float* amount = (const float*)d_in[2];
    const float* count  = (const float*)d_in[3];
    const int*   pairs  = (const int*)  d_in[4];
    const float* W1     = (const float*)d_in[5];
    const float* a1s    = (const float*)d_in[6];
    const float* a1d    = (const float*)d_in[7];
    const float* W2     = (const float*)d_in[8];
    const float* a2s    = (const float*)d_in[9];
    const float* a2d    = (const float*)d_in[10];
    const float* Wb     = (const float*)d_in[11];
    const float* bb     = (const float*)d_in[12];
    float* out = (float*)d_out;
    const int P = in_sizes[4] / 2;   // pairs is [P,2] int32

    float *h1, *o1, *h2, *o2, *hb;
    cudaGetSymbolAddress((void**)&h1, g_h1);
    cudaGetSymbolAddress((void**)&o1, g_o1);
    cudaGetSymbolAddress((void**)&h2, g_h2);
    cudaGetSymbolAddress((void**)&o2, g_o2);
    cudaGetSymbolAddress((void**)&hb, g_hb);

    // sparse structure (adjacency + edge weights) — once, reused by both layers
    build_sparse_k<<<N_NODES, 256>>>(adj, amount, count);

    // ---- layer 1 ----
    {
        dim3 grid(D_HID / BN, N_NODES / BM);
        sgemm_k<<<grid, 256>>>(x, W1, h1, N_NODES, D_HID, D_IN);
    }
    rowdots_k<<<N_NODES, 128>>>(h1, a1s, a1d, D_HID);
    attn_spmm_k<<<N_NODES, 256>>>(h1, o1, D_HID);

    // ---- layer 2 ----
    {
        dim3 grid(D_OUT / BN, N_NODES / BM);
        sgemm_k<<<grid, 256>>>(o1, W2, h2, N_NODES, D_OUT, D_HID);
    }
    rowdots_k<<<N_NODES, 128>>>(h2, a2s, a2d, D_OUT);
    attn_spmm_k<<<N_NODES, 256>>>(h2, o2, D_OUT);

    // ---- link scoring ----
    {
        dim3 grid(D_OUT / BN, N_NODES / BM);
        sgemm_k<<<grid, 256>>>(o2, Wb, hb, N_NODES, D_OUT, D_OUT);
    }
    pairs_k<<<(P * 32 + 255) / 256, 256>>>(pairs, bb, out, P);
}

// round 2
// speedup vs baseline: 1.4794x; 1.4794x over previous
#include <cuda_runtime.h>
#include <cuda_bf16.h>
#include <math.h>

// ============================================================================
// DMAModel: 2-layer weighted GAT + link scoring (sparse formulation).
// ============================================================================

#define N_NODES 4096
#define D_IN    256
#define D_HID   512
#define D_OUT   256
#define CAP     512

// ---------------- scratch (device globals) ----------------------------------
__device__ float g_h1 [N_NODES * D_HID];
__device__ float g_o1 [N_NODES * D_HID];
__device__ float g_h2 [N_NODES * D_OUT];
__device__ float g_o2 [N_NODES * D_OUT];
__device__ float g_hb [N_NODES * D_OUT];
__device__ float g_src[N_NODES];
__device__ float g_dst[N_NODES];
__device__ int   g_cols[(size_t)N_NODES * CAP];
__device__ float g_wv  [(size_t)N_NODES * CAP];
__device__ int   g_cnt [N_NODES];

// ---------------- SGEMM tile config ------------------------------------------
#define BM 128
#define BN 64
#define BK 16
#define TM 8
#define TN 4

// SGEMM body as a device function so it can be used by both the fat kernel
// (overlapped with sparse build) and the standalone kernel.
__device__ __forceinline__ void sgemm_body(const float* __restrict__ A,
                                           const float* __restrict__ B,
                                           float* __restrict__ C,
                                           int N, int K, int bm, int bn,
                                           float (*As)[BM], float (*Bs)[BN])
{
    const int tid = threadIdx.x;
    const int tx = tid & 15;
    const int ty = tid >> 4;
    const int aRow = tid >> 2;
    const int aCol = (tid & 3) * 4;
    const int bRow = tid >> 4;
    const int bCol = (tid & 15) * 4;

    float acc[TM][TN];
    #pragma unroll
    for (int ii = 0; ii < TM; ii++)
        #pragma unroll
        for (int jj = 0; jj < TN; jj++) acc[ii][jj] = 0.0f;

    for (int k0 = 0; k0 < K; k0 += BK) {
        const float4 a0 = *(const float4*)(A + (size_t)(bm + aRow)      * K + k0 + aCol);
        const float4 a1 = *(const float4*)(A + (size_t)(bm + aRow + 64) * K + k0 + aCol);
        As[aCol + 0][aRow]      = a0.x; As[aCol + 1][aRow]      = a0.y;
        As[aCol + 2][aRow]      = a0.z; As[aCol + 3][aRow]      = a0.w;
        As[aCol + 0][aRow + 64] = a1.x; As[aCol + 1][aRow + 64] = a1.y;
        As[aCol + 2][aRow + 64] = a1.z; As[aCol + 3][aRow + 64] = a1.w;
        *(float4*)&Bs[bRow][bCol] =
            *(const float4*)(B + (size_t)(k0 + bRow) * N + bn + bCol);
        __syncthreads();

        #pragma unroll
        for (int k = 0; k < BK; k++) {
            const float4 av0 = *(const float4*)&As[k][ty * TM];
            const float4 av1 = *(const float4*)&As[k][ty * TM + 4];
            const float4 bv  = *(const float4*)&Bs[k][tx * TN];
            const float a[TM] = {av0.x, av0.y, av0.z, av0.w, av1.x, av1.y, av1.z, av1.w};
            const float b[TN] = {bv.x, bv.y, bv.z, bv.w};
            #pragma unroll
            for (int ii = 0; ii < TM; ii++)
                #pragma unroll
                for (int jj = 0; jj < TN; jj++)
                    acc[ii][jj] += a[ii] * b[jj];
        }
        __syncthreads();
    }

    #pragma unroll
    for (int ii = 0; ii < TM; ii++) {
        float4 v = make_float4(acc[ii][0], acc[ii][1], acc[ii][2], acc[ii][3]);
        *(float4*)(C + (size_t)(bm + ty * TM + ii) * N + bn + tx * TN) = v;
    }
}

// ---------------- sparse build body ------------------------------------------
// One block = one row. Each thread reads 16 contiguous columns as 4 float4
// (MLP=4), builds a 16-bit presence mask, block-wide exclusive scan over
// per-thread counts, ordered writes. Fully deterministic (ascending j).
__device__ __forceinline__ void build_row(const float* __restrict__ adj,
                                          const float* __restrict__ amount,
                                          const float* __restrict__ count,
                                          int i)
{
    const int tid  = threadIdx.x;   // 256 threads
    const int lane = tid & 31, warp = tid >> 5;
    __shared__ int s_wsum[8];
    __shared__ int s_total;

    const float4* arow4 = (const float4*)(adj + (size_t)i * N_NODES);
    float4 v[4];
    #pragma unroll
    for (int t = 0; t < 4; t++) v[t] = arow4[tid * 4 + t];

    unsigned m16 = 0;
    #pragma unroll
    for (int t = 0; t < 4; t++) {
        if (v[t].x > 0.0f) m16 |= 1u << (t * 4 + 0);
        if (v[t].y > 0.0f) m16 |= 1u << (t * 4 + 1);
        if (v[t].z > 0.0f) m16 |= 1u << (t * 4 + 2);
        if (v[t].w > 0.0f) m16 |= 1u << (t * 4 + 3);
    }
    const int c = __popc(m16);

    // warp inclusive scan of c
    int x = c;
    #pragma unroll
    for (int o = 1; o < 32; o <<= 1) {
        int y = __shfl_up_sync(0xffffffffu, x, o);
        if (lane >= o) x += y;
    }
    if (lane == 31) s_wsum[warp] = x;
    __syncthreads();
    if (tid == 0) {
        int acc = 0;
        #pragma unroll
        for (int w = 0; w < 8; w++) { int t = s_wsum[w]; s_wsum[w] = acc; acc += t; }
        s_total = acc;
    }
    __syncthreads();

    int pos = s_wsum[warp] + x - c;    // exclusive prefix for this thread
    unsigned mm = m16;
    while (mm) {
        const int b = __ffs(mm) - 1;
        mm &= mm - 1;
        const int j = tid * 16 + b;
        if (pos < CAP) {
            g_cols[(size_t)i * CAP + pos] = j;
            g_wv  [(size_t)i * CAP + pos] =
                0.5f * (amount[(size_t)i * N_NODES + j] +
                        count [(size_t)i * N_NODES + j]);
        }
        pos++;
    }
    if (tid == 0) g_cnt[i] = min(s_total, CAP);
}

// ---------------- fat kernel: sgemm layer-1 overlapped with sparse build -----
// Blocks [0, SG1_BLOCKS) run the x@W1 GEMM; blocks [SG1_BLOCKS, +N_NODES) build
// the sparse structure. DRAM-bound build overlaps compute-bound GEMM.
#define SG1_BLOCKS ((D_HID / BN) * (N_NODES / BM))   // 8*32 = 256
__global__ __launch_bounds__(256) void fat_build_sgemm1_k(
    const float* __restrict__ x,  const float* __restrict__ W1,
    float* __restrict__ h1,
    const float* __restrict__ adj, const float* __restrict__ amount,
    const float* __restrict__ count)
{
    if (blockIdx.x < SG1_BLOCKS) {
        __shared__ float As[BK][BM];
        __shared__ float Bs[BK][BN];
        const int bn = (blockIdx.x & 7) * BN;       // D_HID/BN = 8
        const int bm = (blockIdx.x >> 3) * BM;
        sgemm_body(x, W1, h1, D_HID, D_IN, bm, bn, As, Bs);
    } else {
        build_row(adj, amount, count, blockIdx.x - SG1_BLOCKS);
    }
}

__global__ __launch_bounds__(256) void sgemm_k(const float* __restrict__ A,
                                               const float* __restrict__ B,
                                               float* __restrict__ C,
                                               int N, int K)
{
    __shared__ float As[BK][BM];
    __shared__ float Bs[BK][BN];
    sgemm_body(A, B, C, N, K, blockIdx.y * BM, blockIdx.x * BN, As, Bs);
}

// ---------------- per-row (h@a_src, h@a_dst), vectorized ---------------------
template<int D>
__global__ __launch_bounds__(128) void rowdots_t(const float* __restrict__ h,
                                                 const float* __restrict__ asrc,
                                                 const float* __restrict__ adst)
{
    const int i = blockIdx.x;
    const int tid = threadIdx.x;
    const int lane = tid & 31, warp = tid >> 5;
    constexpr int NF4 = D / 4;
    float s1 = 0.0f, s2 = 0.0f;
    const float4* hr = (const float4*)(h + (size_t)i * D);
    const float4* a4 = (const float4*)asrc;
    const float4* b4 = (const float4*)adst;
    #pragma unroll
    for (int t = tid; t < NF4; t += 128) {
        const float4 v = hr[t], a = a4[t], b = b4[t];
        s1 += v.x * a.x + v.y * a.y + v.z * a.z + v.w * a.w;
        s2 += v.x * b.x + v.y * b.y + v.z * b.z + v.w * b.w;
    }
    #pragma unroll
    for (int o = 16; o > 0; o >>= 1) {
        s1 += __shfl_down_sync(0xffffffffu, s1, o);
        s2 += __shfl_down_sync(0xffffffffu, s2, o);
    }
    __shared__ float r1[4], r2[4];
    if (lane == 0) { r1[warp] = s1; r2[warp] = s2; }
    __syncthreads();
    if (tid == 0) {
        g_src[i] = r1[0] + r1[1] + r1[2] + r1[3];
        g_dst[i] = r2[0] + r2[1] + r2[2] + r2[3];
    }
}

// ---------------- fused sparse attention softmax + SpMM + ELU ----------------
// 128 threads/block; split-k groups keep all threads busy when D/4 < 128.
template<int D>
__global__ __launch_bounds__(128) void attn_spmm_t(const float* __restrict__ h,
                                                   float* __restrict__ out)
{
    constexpr int TPB = 128;
    constexpr int NF4 = D / 4;            // 128 (D=512) or 64 (D=256)
    constexpr int NGR = TPB / NF4;        // 1 or 2
    const int i = blockIdx.x;
    const int tid = threadIdx.x;
    const int cnt = g_cnt[i];

    __shared__ float s_p  [CAP];
    __shared__ int   s_off[CAP];
    __shared__ float red  [TPB];

    const float si = g_src[i];
    float lmax = -3.4e38f;
    for (int k = tid; k < cnt; k += TPB) {
        const int c = g_cols[(size_t)i * CAP + k];
        s_off[k] = c * D;
        float e = si + g_dst[c];
        e = (e >= 0.0f) ? e : 0.2f * e;
        s_p[k] = e;
        lmax = fmaxf(lmax, e);
    }
    red[tid] = lmax;
    __syncthreads();
    #pragma unroll
    for (int s = TPB / 2; s > 0; s >>= 1) {
        if (tid < s) red[tid] = fmaxf(red[tid], red[tid + s]);
        __syncthreads();
    }
    const float m = red[0];
    __syncthreads();

    float lsum = 0.0f;
    for (int k = tid; k < cnt; k += TPB) {
        const float ex = expf(s_p[k] - m);
        s_p[k] = ex;
        lsum += ex;
    }
    red[tid] = lsum;
    __syncthreads();
    #pragma unroll
    for (int s = TPB / 2; s > 0; s >>= 1) {
        if (tid < s) red[tid] += red[tid + s];
        __syncthreads();
    }
    const float inv = (cnt > 0) ? (1.0f / red[0]) : 0.0f;
    __syncthreads();

    for (int k = tid; k < cnt; k += TPB)
        s_p[k] = s_p[k] * inv * g_wv[(size_t)i * CAP + k];
    __syncthreads();

    // aggregation: thread (g, d4) accumulates float4 over k strided by NGR
    const int g  = tid / NF4;
    const int d4 = tid % NF4;
    float4 acc = make_float4(0.f, 0.f, 0.f, 0.f);
    #pragma unroll 4
    for (int k = g; k < cnt; k += NGR) {
        const float4 v = *(const float4*)(h + s_off[k] + (d4 << 2));
        const float p = s_p[k];
        acc.x += p * v.x; acc.y += p * v.y;
        acc.z += p * v.z; acc.w += p * v.w;
    }
    if (NGR > 1) {
        __shared__ float4 s_acc[TPB];
        if (g > 0) s_acc[tid] = acc;
        __syncthreads();
        if (g == 0) {
            const float4 o = s_acc[tid + NF4];
            acc.x += o.x; acc.y += o.y; acc.z += o.z; acc.w += o.w;
        }
    }
    if (g == 0) {
        float4 r;
        r.x = (acc.x > 0.0f) ? acc.x : expm1f(acc.x);
        r.y = (acc.y > 0.0f) ? acc.y : expm1f(acc.y);
        r.z = (acc.z > 0.0f) ? acc.z : expm1f(acc.z);
        r.w = (acc.w > 0.0f) ? acc.w : expm1f(acc.w);
        *(float4*)(out + (size_t)i * D + (d4 << 2)) = r;
    }
}

// ---------------- pair scoring: sigmoid(H[i].h[j] + bb) ----------------------
__global__ void pairs_k(const int* __restrict__ pairs,
                        const float* __restrict__ bb,
                        float* __restrict__ out, int P)
{
    const int wid  = (blockIdx.x * blockDim.x + threadIdx.x) >> 5;
    const int lane = threadIdx.x & 31;
    if (wid >= P) return;
    const int i = pairs[2 * wid + 0];
    const int j = pairs[2 * wid + 1];
    const float4* ra = (const float4*)(g_hb + (size_t)i * D_OUT);
    const float4* rb = (const float4*)(g_o2 + (size_t)j * D_OUT);
    float s = 0.0f;
    #pragma unroll
    for (int t = lane; t < D_OUT / 4; t += 32) {
        const float4 a = ra[t], b = rb[t];
        s += a.x * b.x + a.y * b.y + a.z * b.z + a.w * b.w;
    }
    #pragma unroll
    for (int o = 16; o > 0; o >>= 1) s += __shfl_down_sync(0xffffffffu, s, o);
    if (lane == 0) out[wid] = 1.0f / (1.0f + expf(-(s + bb[0])));
}

// ============================================================================
extern "C" void kernel_launch(void* const* d_in, const int* in_sizes, int n_in,
                              void* d_out, int out_size)
{
    const float* x      = (const float*)d_in[0];
    const float* adj    = (const float*)d_in[1];
    const float* amount = (const float*)d_in[2];
    const float* count  = (const float*)d_in[3];
    const int*   pairs  = (const int*)  d_in[4];
    const float* W1     = (const float*)d_in[5];
    const float* a1s    = (const float*)d_in[6];
    const float* a1d    = (const float*)d_in[7];
    const float* W2     = (const float*)d_in[8];
    const float* a2s    = (const float*)d_in[9];
    const float* a2d    = (const float*)d_in[10];
    const float* Wb     = (const float*)d_in[11];
    const float* bb     = (const float*)d_in[12];
    float* out = (float*)d_out;
    const int P = in_sizes[4] / 2;

    float *h1, *o1, *h2, *o2, *hb;
    cudaGetSymbolAddress((void**)&h1, g_h1);
    cudaGetSymbolAddress((void**)&o1, g_o1);
    cudaGetSymbolAddress((void**)&h2, g_h2);
    cudaGetSymbolAddress((void**)&o2, g_o2);
    cudaGetSymbolAddress((void**)&hb, g_hb);

    // layer 1 GEMM overlapped with sparse structure build
    fat_build_sgemm1_k<<<SG1_BLOCKS + N_NODES, 256>>>(x, W1, h1, adj, amount, count);
    rowdots_t<D_HID><<<N_NODES, 128>>>(h1, a1s, a1d);
    attn_spmm_t<D_HID><<<N_NODES, 128>>>(h1, o1);

    // layer 2
    {
        dim3 grid(D_OUT / BN, N_NODES / BM);
        sgemm_k<<<grid, 256>>>(o1, W2, h2, D_OUT, D_HID);
    }
    rowdots_t<D_OUT><<<N_NODES, 128>>>(h2, a2s, a2d);
    attn_spmm_t<D_OUT><<<N_NODES, 128>>>(h2, o2);

    // link scoring
    {
        dim3 grid(D_OUT / BN, N_NODES / BM);
        sgemm_k<<<grid, 256>>>(o2, Wb, hb, D_OUT, D_OUT);
    }
    pairs_k<<<(P * 32 + 255) / 256, 256>>>(pairs, bb, out, P);
}

// round 3
// speedup vs baseline: 1.5933x; 1.0770x over previous
#include <cuda_runtime.h>
#include <cuda_bf16.h>
#include <math.h>

// ============================================================================
// DMAModel: 2-layer weighted GAT + link scoring (sparse formulation).
// ============================================================================

#define N_NODES 4096
#define D_IN    256
#define D_HID   512
#define D_OUT   256
#define CAP     512

// ---------------- scratch (device globals) ----------------------------------
__device__ float g_h1 [N_NODES * D_HID];
__device__ float g_o1 [N_NODES * D_HID];
__device__ float g_h2 [N_NODES * D_OUT];
__device__ float g_o2 [N_NODES * D_OUT];
__device__ float g_hb [N_NODES * D_OUT];
__device__ float g_src[N_NODES];
__device__ float g_dst[N_NODES];
__device__ int   g_cols[(size_t)N_NODES * CAP];
__device__ float g_wv  [(size_t)N_NODES * CAP];
__device__ int   g_cnt [N_NODES];

// ---------------- SGEMM: 64x64 tile, double-buffered, 256 threads ------------
#define BM 64
#define BN 64
#define BK 16
#define BMP (BM + 4)          // pad to reduce STS bank conflicts on transposed A

// Per block: tile C[64,64]; thread (ty,tx) owns 4x4 microtile.
// A-tile loaded transposed into As[k][m]; B-tile row-major Bs[k][n].
__device__ __forceinline__ void sgemm_body(const float* __restrict__ A,
                                           const float* __restrict__ B,
                                           float* __restrict__ C,
                                           int N, int K, int bm, int bn,
                                           float (*As)[BK][BMP],
                                           float (*Bs)[BK][BN])
{
    const int tid = threadIdx.x;
    const int tx = tid & 15;             // n-dir
    const int ty = tid >> 4;             // m-dir
    const int aRow = tid >> 2;           // 0..63
    const int aCol = (tid & 3) * 4;      // 0,4,8,12
    const int bRow = tid >> 4;           // 0..15
    const int bCol = (tid & 15) * 4;     // 0..60

    const float* Ag = A + (size_t)(bm + aRow) * K + aCol;
    const float* Bg = B + (size_t)bRow * N + bn + bCol;

    float acc[4][4];
    #pragma unroll
    for (int i = 0; i < 4; i++)
        #pragma unroll
        for (int j = 0; j < 4; j++) acc[i][j] = 0.0f;

    // preload tile 0
    float4 a_n = *(const float4*)Ag;
    float4 b_n = *(const float4*)Bg;
    {
        (*As)[aCol + 0][aRow] = a_n.x; (*As)[aCol + 1][aRow] = a_n.y;
        (*As)[aCol + 2][aRow] = a_n.z; (*As)[aCol + 3][aRow] = a_n.w;
        *(float4*)&(*Bs)[bRow][bCol] = b_n;
    }
    __syncthreads();

    int buf = 0;
    for (int k0 = BK; k0 < K; k0 += BK) {
        // prefetch next tile into registers
        a_n = *(const float4*)(Ag + k0);
        b_n = *(const float4*)(Bg + (size_t)k0 * N);

        // compute on current buffer
        #pragma unroll
        for (int k = 0; k < BK; k++) {
            const float4 av = *(const float4*)&As[buf][k][ty * 4];
            const float4 bv = *(const float4*)&Bs[buf][k][tx * 4];
            const float a[4] = {av.x, av.y, av.z, av.w};
            const float b[4] = {bv.x, bv.y, bv.z, bv.w};
            #pragma unroll
            for (int i = 0; i < 4; i++)
                #pragma unroll
                for (int j = 0; j < 4; j++)
                    acc[i][j] += a[i] * b[j];
        }

        // store prefetched tile into other buffer
        buf ^= 1;
        As[buf][aCol + 0][aRow] = a_n.x; As[buf][aCol + 1][aRow] = a_n.y;
        As[buf][aCol + 2][aRow] = a_n.z; As[buf][aCol + 3][aRow] = a_n.w;
        *(float4*)&Bs[buf][bRow][bCol] = b_n;
        __syncthreads();
    }

    // last tile
    #pragma unroll
    for (int k = 0; k < BK; k++) {
        const float4 av = *(const float4*)&As[buf][k][ty * 4];
        const float4 bv = *(const float4*)&Bs[buf][k][tx * 4];
        const float a[4] = {av.x, av.y, av.z, av.w};
        const float b[4] = {bv.x, bv.y, bv.z, bv.w};
        #pragma unroll
        for (int i = 0; i < 4; i++)
            #pragma unroll
            for (int j = 0; j < 4; j++)
                acc[i][j] += a[i] * b[j];
    }

    #pragma unroll
    for (int i = 0; i < 4; i++) {
        float4 v = make_float4(acc[i][0], acc[i][1], acc[i][2], acc[i][3]);
        *(float4*)(C + (size_t)(bm + ty * 4 + i) * N + bn + tx * 4) = v;
    }
}

// ---------------- sparse build body ------------------------------------------
__device__ __forceinline__ void build_row(const float* __restrict__ adj,
                                          const float* __restrict__ amount,
                                          const float* __restrict__ count,
                                          int i)
{
    const int tid  = threadIdx.x;   // 256 threads
    const int lane = tid & 31, warp = tid >> 5;
    __shared__ int s_wsum[8];
    __shared__ int s_total;

    const float4* arow4 = (const float4*)(adj + (size_t)i * N_NODES);
    float4 v[4];
    #pragma unroll
    for (int t = 0; t < 4; t++) v[t] = arow4[tid * 4 + t];

    unsigned m16 = 0;
    #pragma unroll
    for (int t = 0; t < 4; t++) {
        if (v[t].x > 0.0f) m16 |= 1u << (t * 4 + 0);
        if (v[t].y > 0.0f) m16 |= 1u << (t * 4 + 1);
        if (v[t].z > 0.0f) m16 |= 1u << (t * 4 + 2);
        if (v[t].w > 0.0f) m16 |= 1u << (t * 4 + 3);
    }
    const int c = __popc(m16);

    int x = c;
    #pragma unroll
    for (int o = 1; o < 32; o <<= 1) {
        int y = __shfl_up_sync(0xffffffffu, x, o);
        if (lane >= o) x += y;
    }
    if (lane == 31) s_wsum[warp] = x;
    __syncthreads();
    if (tid == 0) {
        int acc = 0;
        #pragma unroll
        for (int w = 0; w < 8; w++) { int t = s_wsum[w]; s_wsum[w] = acc; acc += t; }
        s_total = acc;
    }
    __syncthreads();

    int pos = s_wsum[warp] + x - c;
    unsigned mm = m16;
    while (mm) {
        const int b = __ffs(mm) - 1;
        mm &= mm - 1;
        const int j = tid * 16 + b;
        if (pos < CAP) {
            g_cols[(size_t)i * CAP + pos] = j;
            g_wv  [(size_t)i * CAP + pos] =
                0.5f * (amount[(size_t)i * N_NODES + j] +
                        count [(size_t)i * N_NODES + j]);
        }
        pos++;
    }
    if (tid == 0) g_cnt[i] = min(s_total, CAP);
}

// ---------------- fat kernel: layer-1 GEMM overlapped with sparse build ------
#define SG1_BLOCKS ((D_HID / BN) * (N_NODES / BM))   // 8*64 = 512
__global__ __launch_bounds__(256) void fat_build_sgemm1_k(
    const float* __restrict__ x,  const float* __restrict__ W1,
    float* __restrict__ h1,
    const float* __restrict__ adj, const float* __restrict__ amount,
    const float* __restrict__ count)
{
    if (blockIdx.x < SG1_BLOCKS) {
        __shared__ float As[2][BK][BMP];
        __shared__ float Bs[2][BK][BN];
        const int bn = (blockIdx.x & 7) * BN;       // D_HID/BN = 8
        const int bm = (blockIdx.x >> 3) * BM;
        sgemm_body(x, W1, h1, D_HID, D_IN, bm, bn, As[0] ? As : As, Bs);
    } else {
        build_row(adj, amount, count, blockIdx.x - SG1_BLOCKS);
    }
}

__global__ __launch_bounds__(256) void sgemm_k(const float* __restrict__ A,
                                               const float* __restrict__ B,
                                               float* __restrict__ C,
                                               int N, int K)
{
    __shared__ float As[2][BK][BMP];
    __shared__ float Bs[2][BK][BN];
    sgemm_body(A, B, C, N, K, blockIdx.y * BM, blockIdx.x * BN, As, Bs);
}

// ---------------- per-row (h@a_src, h@a_dst), vectorized ---------------------
template<int D>
__global__ __launch_bounds__(128) void rowdots_t(const float* __restrict__ h,
                                                 const float* __restrict__ asrc,
                                                 const float* __restrict__ adst)
{
    const int i = blockIdx.x;
    const int tid = threadIdx.x;
    const int lane = tid & 31, warp = tid >> 5;
    constexpr int NF4 = D / 4;
    float s1 = 0.0f, s2 = 0.0f;
    const float4* hr = (const float4*)(h + (size_t)i * D);
    const float4* a4 = (const float4*)asrc;
    const float4* b4 = (const float4*)adst;
    #pragma unroll
    for (int t = tid; t < NF4; t += 128) {
        const float4 v = hr[t], a = a4[t], b = b4[t];
        s1 += v.x * a.x + v.y * a.y + v.z * a.z + v.w * a.w;
        s2 += v.x * b.x + v.y * b.y + v.z * b.z + v.w * b.w;
    }
    #pragma unroll
    for (int o = 16; o > 0; o >>= 1) {
        s1 += __shfl_down_sync(0xffffffffu, s1, o);
        s2 += __shfl_down_sync(0xffffffffu, s2, o);
    }
    __shared__ float r1[4], r2[4];
    if (lane == 0) { r1[warp] = s1; r2[warp] = s2; }
    __syncthreads();
    if (tid == 0) {
        g_src[i] = r1[0] + r1[1] + r1[2] + r1[3];
        g_dst[i] = r2[0] + r2[1] + r2[2] + r2[3];
    }
}

// ---------------- fused sparse attention softmax + SpMM + ELU ----------------
template<int D>
__global__ __launch_bounds__(128) void attn_spmm_t(const float* __restrict__ h,
                                                   float* __restrict__ out)
{
    constexpr int TPB = 128;
    constexpr int NF4 = D / 4;            // 128 (D=512) or 64 (D=256)
    constexpr int NGR = TPB / NF4;        // 1 or 2
    const int i = blockIdx.x;
    const int tid = threadIdx.x;
    const int cnt = g_cnt[i];

    __shared__ float s_p  [CAP];
    __shared__ int   s_off[CAP];
    __shared__ float red  [TPB];

    const float si = g_src[i];
    float lmax = -3.4e38f;
    for (int k = tid; k < cnt; k += TPB) {
        const int c = g_cols[(size_t)i * CAP + k];
        s_off[k] = c * D;
        float e = si + g_dst[c];
        e = (e >= 0.0f) ? e : 0.2f * e;
        s_p[k] = e;
        lmax = fmaxf(lmax, e);
    }
    red[tid] = lmax;
    __syncthreads();
    #pragma unroll
    for (int s = TPB / 2; s > 0; s >>= 1) {
        if (tid < s) red[tid] = fmaxf(red[tid], red[tid + s]);
        __syncthreads();
    }
    const float m = red[0];
    __syncthreads();

    float lsum = 0.0f;
    for (int k = tid; k < cnt; k += TPB) {
        const float ex = expf(s_p[k] - m);
        s_p[k] = ex;
        lsum += ex;
    }
    red[tid] = lsum;
    __syncthreads();
    #pragma unroll
    for (int s = TPB / 2; s > 0; s >>= 1) {
        if (tid < s) red[tid] += red[tid + s];
        __syncthreads();
    }
    const float inv = (cnt > 0) ? (1.0f / red[0]) : 0.0f;
    __syncthreads();

    for (int k = tid; k < cnt; k += TPB)
        s_p[k] = s_p[k] * inv * g_wv[(size_t)i * CAP + k];
    __syncthreads();

    const int g  = tid / NF4;
    const int d4 = tid % NF4;
    float4 acc = make_float4(0.f, 0.f, 0.f, 0.f);
    #pragma unroll 4
    for (int k = g; k < cnt; k += NGR) {
        const float4 v = *(const float4*)(h + s_off[k] + (d4 << 2));
        const float p = s_p[k];
        acc.x += p * v.x; acc.y += p * v.y;
        acc.z += p * v.z; acc.w += p * v.w;
    }
    if (NGR > 1) {
        __shared__ float4 s_acc[TPB];
        if (g > 0) s_acc[tid] = acc;
        __syncthreads();
        if (g == 0) {
            const float4 o = s_acc[tid + NF4];
            acc.x += o.x; acc.y += o.y; acc.z += o.z; acc.w += o.w;
        }
    }
    if (g == 0) {
        float4 r;
        r.x = (acc.x > 0.0f) ? acc.x : expm1f(acc.x);
        r.y = (acc.y > 0.0f) ? acc.y : expm1f(acc.y);
        r.z = (acc.z > 0.0f) ? acc.z : expm1f(acc.z);
        r.w = (acc.w > 0.0f) ? acc.w : expm1f(acc.w);
        *(float4*)(out + (size_t)i * D + (d4 << 2)) = r;
    }
}

// ---------------- pair scoring: sigmoid(H[i].h[j] + bb) ----------------------
__global__ void pairs_k(const int* __restrict__ pairs,
                        const float* __restrict__ bb,
                        float* __restrict__ out, int P)
{
    const int wid  = (blockIdx.x * blockDim.x + threadIdx.x) >> 5;
    const int lane = threadIdx.x & 31;
    if (wid >= P) return;
    const int i = pairs[2 * wid + 0];
    const int j = pairs[2 * wid + 1];
    const float4* ra = (const float4*)(g_hb + (size_t)i * D_OUT);
    const float4* rb = (const float4*)(g_o2 + (size_t)j * D_OUT);
    float s = 0.0f;
    #pragma unroll
    for (int t = lane; t < D_OUT / 4; t += 32) {
        const float4 a = ra[t], b = rb[t];
        s += a.x * b.x + a.y * b.y + a.z * b.z + a.w * b.w;
    }
    #pragma unroll
    for (int o = 16; o > 0; o >>= 1) s += __shfl_down_sync(0xffffffffu, s, o);
    if (lane == 0) out[wid] = 1.0f / (1.0f + expf(-(s + bb[0])));
}

// ============================================================================
extern "C" void kernel_launch(void* const* d_in, const int* in_sizes, int n_in,
                              void* d_out, int out_size)
{
    const float* x      = (const float*)d_in[0];
    const float* adj    = (const float*)d_in[1];
    const float* amount = (const float*)d_in[2];
    const float* count  = (const float*)d_in[3];
    const int*   pairs  = (const int*)  d_in[4];
    const float* W1     = (const float*)d_in[5];
    const float* a1s    = (const float*)d_in[6];
    const float* a1d    = (const float*)d_in[7];
    const float* W2     = (const float*)d_in[8];
    const float* a2s    = (const float*)d_in[9];
    const float* a2d    = (const float*)d_in[10];
    const float* Wb     = (const float*)d_in[11];
    const float* bb     = (const float*)d_in[12];
    float* out = (float*)d_out;
    const int P = in_sizes[4] / 2;

    float *h1, *o1, *h2, *o2, *hb;
    cudaGetSymbolAddress((void**)&h1, g_h1);
    cudaGetSymbolAddress((void**)&o1, g_o1);
    cudaGetSymbolAddress((void**)&h2, g_h2);
    cudaGetSymbolAddress((void**)&o2, g_o2);
    cudaGetSymbolAddress((void**)&hb, g_hb);

    // layer 1 GEMM overlapped with sparse structure build
    fat_build_sgemm1_k<<<SG1_BLOCKS + N_NODES, 256>>>(x, W1, h1, adj, amount, count);
    rowdots_t<D_HID><<<N_NODES, 128>>>(h1, a1s, a1d);
    attn_spmm_t<D_HID><<<N_NODES, 128>>>(h1, o1);

    // layer 2
    {
        dim3 grid(D_OUT / BN, N_NODES / BM);
        sgemm_k<<<grid, 256>>>(o1, W2, h2, D_OUT, D_HID);
    }
    rowdots_t<D_OUT><<<N_NODES, 128>>>(h2, a2s, a2d);
    attn_spmm_t<D_OUT><<<N_NODES, 128>>>(h2, o2);

    // link scoring
    {
        dim3 grid(D_OUT / BN, N_NODES / BM);
        sgemm_k<<<grid, 256>>>(o2, Wb, hb, D_OUT, D_OUT);
    }
    pairs_k<<<(P * 32 + 255) / 256, 256>>>(pairs, bb, out, P);
}